// round 10
// baseline (speedup 1.0000x reference)
#include <cuda_runtime.h>
#include <cstdint>

#define NT 60
#define ND 36
#define NL 10
#define NS 9
#define NO 8
#define MIN_ (NT*NL + NS) // 609
#define TPB 64
#define NBJ 16384
#define ROWS ((size_t)NBJ * NT)   // 983040

typedef unsigned long long u64;

// 126 MB scratch: per (b,t) row of 32 floats: au[10]*L2E, ar[10]*L2E, an[10], pad[2]
__device__ __align__(128) float g_pre[ROWS * 32];

__device__ __forceinline__ float ex2(float x) {
    float r; asm("ex2.approx.ftz.f32 %0, %1;" : "=f"(r) : "f"(x)); return r;
}
__device__ __forceinline__ float frcp(float x) {
    float r; asm("rcp.approx.ftz.f32 %0, %1;" : "=f"(r) : "f"(x)); return r;
}
__device__ __forceinline__ void ffma2(u64& d, u64 a, u64 b) {
    asm("fma.rn.f32x2 %0, %1, %2, %0;" : "+l"(d) : "l"(a), "l"(b));
}
__device__ __forceinline__ u64 pack2(float v) {
    u64 r; asm("mov.b64 %0, {%1, %1};" : "=l"(r) : "f"(v)); return r;
}
__device__ __forceinline__ float2 unpack2(u64 v) {
    float2 f; asm("mov.b64 {%0, %1}, %2;" : "=f"(f.x), "=f"(f.y) : "l"(v)); return f;
}
__device__ __forceinline__ uint32_t smem_u32(const void* p) {
    return (uint32_t)__cvta_generic_to_shared(p);
}
__device__ __forceinline__ void cpasync16(uint32_t dst, const float* src) {
    asm volatile("cp.async.cg.shared.global [%0], [%1], 16;" :: "r"(dst), "l"(src));
}
__device__ __forceinline__ void cpcommit() {
    asm volatile("cp.async.commit_group;" ::: "memory");
}
template<int N> __device__ __forceinline__ void cpwait() {
    asm volatile("cp.async.wait_group %0;" :: "n"(N) : "memory");
}

// ============================================================================
// Kernel A: pre-activation GEMM, smem-staged I/O, ulonglong2 weight reads
//   row r = (b*NT + t): [ (x@WuX+bu)*L2E | (x@WrX+br)*L2E | x@WnX+bn | pad2 ]
// ============================================================================
__global__ __launch_bounds__(256) void preact_kernel(
    const float* __restrict__ data,
    const float* __restrict__ gWu, const float* __restrict__ gbu,
    const float* __restrict__ gWr, const float* __restrict__ gbr,
    const float* __restrict__ gWn, const float* __restrict__ gbn)
{
    __shared__ __align__(16) float W[ND][32];   // [k][u(10) r(10) n(10) pad2]
    __shared__ __align__(16) float bias[32];
    __shared__ __align__(16) float buf[256 * 37];  // in: rows padded to 37; out: 33
    const int tid = threadIdx.x;
    const float L2E = 1.4426950408889634f;

    for (int i = tid; i < ND * NL; i += 256) {
        int k = i / NL, j = i - k * NL;
        W[k][j]      = gWu[(NL + k) * NL + j] * L2E;
        W[k][10 + j] = gWr[(NL + k) * NL + j] * L2E;
        W[k][20 + j] = gWn[(NL + k) * NL + j];
    }
    for (int i = tid; i < ND * 2; i += 256) W[i / 2][30 + (i & 1)] = 0.f;
    if (tid < NL) {
        bias[tid]      = gbu[tid] * L2E;
        bias[10 + tid] = gbr[tid] * L2E;
        bias[20 + tid] = gbn[tid];
    }
    if (tid < 2) bias[30 + tid] = 0.f;

    // ---- coalesced load of 256 contiguous rows (36 KB) into padded smem ----
    const size_t fbase = (size_t)blockIdx.x * 256 * ND;
    const float4* src4 = reinterpret_cast<const float4*>(data + fbase);
#pragma unroll
    for (int i = 0; i < 9; i++) {
        float4 v = src4[tid + 256 * i];
        int g = 4 * (tid + 256 * i);
        float vv[4] = {v.x, v.y, v.z, v.w};
#pragma unroll
        for (int j = 0; j < 4; j++) {
            int gg = g + j;
            buf[gg + gg / ND] = vv[j];     // row*37 + col
        }
    }
    __syncthreads();

    // ---- compute: 1 row/thread; weights via direct ulonglong2 LDS (no movs) ----
    const float* xr = buf + tid * 37;
    u64 acc[15];
    const u64* bp = (const u64*)bias;
#pragma unroll
    for (int p = 0; p < 15; p++) acc[p] = bp[p];

#pragma unroll
    for (int k = 0; k < ND; k++) {
        u64 xp = pack2(xr[k]);
        const ulonglong2* w2 = (const ulonglong2*)W[k];
        ulonglong2 wa = w2[0], wb = w2[1], wc = w2[2];
        ulonglong2 wd = w2[3], we_ = w2[4], wf = w2[5], wg = w2[6];
        u64 w14 = ((const u64*)W[k])[14];
        ffma2(acc[0],  xp, wa.x);  ffma2(acc[1],  xp, wa.y);
        ffma2(acc[2],  xp, wb.x);  ffma2(acc[3],  xp, wb.y);
        ffma2(acc[4],  xp, wc.x);  ffma2(acc[5],  xp, wc.y);
        ffma2(acc[6],  xp, wd.x);  ffma2(acc[7],  xp, wd.y);
        ffma2(acc[8],  xp, we_.x); ffma2(acc[9],  xp, we_.y);
        ffma2(acc[10], xp, wf.x);  ffma2(acc[11], xp, wf.y);
        ffma2(acc[12], xp, wg.x);  ffma2(acc[13], xp, wg.y);
        ffma2(acc[14], xp, w14);
    }
    __syncthreads();   // input tile reads done; reuse buf as output staging

    // ---- write results to padded-33 smem rows (conflict-free) ----
    float* orow = buf + tid * 33;
#pragma unroll
    for (int p = 0; p < 15; p++) {
        float2 f = unpack2(acc[p]);
        orow[2 * p] = f.x;
        orow[2 * p + 1] = f.y;
    }
    orow[30] = 0.f; orow[31] = 0.f;
    __syncthreads();

    // ---- coalesced store of the 32 KB output tile ----
    float4* dst4 = reinterpret_cast<float4*>(g_pre + (size_t)blockIdx.x * 256 * 32);
#pragma unroll
    for (int i = 0; i < 8; i++) {
        int g4 = tid + 256 * i;
        int rl = g4 >> 3, q = g4 & 7;
        const float* s = buf + rl * 33 + q * 4;
        dst4[g4] = make_float4(s[0], s[1], s[2], s[3]);
    }
}

// ============================================================================
// Kernel B: recurrent scan (unchanged)
// ============================================================================
struct __align__(16) SWB {
    float Wu[NL][12];     // yo-part rows, ×L2E
    float Wr[NL][12];     // ×L2E
    float Wn[NL][12];     // candidate rows, unscaled
    float Wo[NL][12];     // ×2*L2E
    float Wm[MIN_][NO];
    float bo[12];         // ×2*L2E
    float bm[NO];
    float dts[NT];
};

__global__ __launch_bounds__(TPB) void dgm2_kernel(
    const float* __restrict__ ts,
    const float* __restrict__ stat,
    const float* __restrict__ gWu,
    const float* __restrict__ gWr,
    const float* __restrict__ gWn,
    const float* __restrict__ gWo, const float* __restrict__ gbo,
    const float* __restrict__ gWm, const float* __restrict__ gbm,
    float* __restrict__ out)
{
    __shared__ SWB sw;
    __shared__ __align__(16) u64 pre[2][8][TPB][2];
    const int tid = threadIdx.x;
    const float L2E = 1.4426950408889634f;

    for (int i = tid; i < NL * NL; i += TPB) {
        int r = i / NL, c = i - r * NL;
        sw.Wu[r][c] = gWu[i] * L2E;
        sw.Wr[r][c] = gWr[i] * L2E;
        sw.Wn[r][c] = gWn[i];
        sw.Wo[r][c] = gWo[i] * (2.f * L2E);
    }
    for (int i = tid; i < MIN_ * NO; i += TPB) (&sw.Wm[0][0])[i] = gWm[i];
    if (tid < 12) sw.bo[tid] = 0.f;
    __syncthreads();
    if (tid < NL) sw.bo[tid] = gbo[tid] * (2.f * L2E);
    if (tid < NO) sw.bm[tid] = gbm[tid];
    for (int i = tid; i < NT; i += TPB)
        sw.dts[i] = (i == 0) ? 0.01f : (ts[i] - ts[i - 1]);
    __syncthreads();

    const int b = blockIdx.x * TPB + tid;
    const float* pg = g_pre + (size_t)b * NT * 32;

#pragma unroll
    for (int c = 0; c < 8; c++)
        cpasync16(smem_u32(&pre[0][c][tid][0]), pg + 4 * c);
    cpcommit();

    float y[NL];
    u64 ynp[NL];
    u64 acc2[4];
#pragma unroll
    for (int j = 0; j < NL; j++) { y[j] = 0.f; ynp[j] = 0ull; }
#pragma unroll
    for (int o = 0; o < 4; o++) acc2[o] = 0ull;

    const u64* bop = (const u64*)sw.bo;

#pragma unroll 1
    for (int t = 0; t < NT; t++) {
        if (t + 1 < NT) {
            const int nb = (t + 1) & 1;
            const float* src = pg + (size_t)(t + 1) * 32;
#pragma unroll
            for (int c = 0; c < 8; c++)
                cpasync16(smem_u32(&pre[nb][c][tid][0]), src + 4 * c);
            cpcommit();
            cpwait<1>();
        } else {
            cpwait<0>();
        }
        const float dt = sw.dts[t];
        const float dt2 = 2.f * dt;

        // ---- ODE Euler ----
        u64 og2[5];
#pragma unroll
        for (int p = 0; p < 5; p++) og2[p] = bop[p];
#pragma unroll
        for (int k = 0; k < NL; k++) {
            const ulonglong2* w = (const ulonglong2*)sw.Wo[k];
            ulonglong2 w01 = w[0], w23 = w[1];
            u64 w4 = ((const u64*)sw.Wo[k])[4];
            ffma2(og2[0], ynp[k], w01.x);
            ffma2(og2[1], ynp[k], w01.y);
            ffma2(og2[2], ynp[k], w23.x);
            ffma2(og2[3], ynp[k], w23.y);
            ffma2(og2[4], ynp[k], w4);
        }
        float yo[NL];
#pragma unroll
        for (int p = 0; p < 5; p++) {
            float2 g = unpack2(og2[p]);
            yo[2 * p]     = (y[2 * p] + dt)     - dt2 * frcp(ex2(g.x) + 1.f);
            yo[2 * p + 1] = (y[2 * p + 1] + dt) - dt2 * frcp(ex2(g.y) + 1.f);
        }
        u64 yop[NL];
#pragma unroll
        for (int k = 0; k < NL; k++) yop[k] = pack2(yo[k]);

        // ---- gate accumulators init from streamed pre-activations ----
        u64 pv[16];
        const int cb = t & 1;
#pragma unroll
        for (int c = 0; c < 8; c++) {
            ulonglong2 v = *(const ulonglong2*)&pre[cb][c][tid][0];
            pv[2 * c] = v.x; pv[2 * c + 1] = v.y;
        }
        u64 au2[5], ar2[5], an2[5];
#pragma unroll
        for (int p = 0; p < 5; p++) {
            au2[p] = pv[p];
            ar2[p] = pv[5 + p];
            an2[p] = pv[10 + p];
        }

        // yo part for update/reset
#pragma unroll
        for (int k = 0; k < NL; k++) {
            const ulonglong2* wu = (const ulonglong2*)sw.Wu[k];
            const ulonglong2* wr = (const ulonglong2*)sw.Wr[k];
            ulonglong2 u01 = wu[0], u23 = wu[1];
            ulonglong2 r01 = wr[0], r23 = wr[1];
            u64 u4 = ((const u64*)sw.Wu[k])[4];
            u64 r4 = ((const u64*)sw.Wr[k])[4];
            ffma2(au2[0], yop[k], u01.x); ffma2(au2[1], yop[k], u01.y);
            ffma2(au2[2], yop[k], u23.x); ffma2(au2[3], yop[k], u23.y);
            ffma2(au2[4], yop[k], u4);
            ffma2(ar2[0], yop[k], r01.x); ffma2(ar2[1], yop[k], r01.y);
            ffma2(ar2[2], yop[k], r23.x); ffma2(ar2[3], yop[k], r23.y);
            ffma2(ar2[4], yop[k], r4);
        }
        // sigmoid (inputs pre-scaled by log2e)
        float u[NL], r[NL];
#pragma unroll
        for (int p = 0; p < 5; p++) {
            float2 a = unpack2(au2[p]);
            float2 rr = unpack2(ar2[p]);
            u[2 * p]     = frcp(1.f + ex2(-a.x));
            u[2 * p + 1] = frcp(1.f + ex2(-a.y));
            r[2 * p]     = frcp(1.f + ex2(-rr.x));
            r[2 * p + 1] = frcp(1.f + ex2(-rr.y));
        }
        // candidate (yo*r part)
#pragma unroll
        for (int k = 0; k < NL; k++) {
            u64 cp = pack2(yo[k] * r[k]);
            const ulonglong2* wn = (const ulonglong2*)sw.Wn[k];
            ulonglong2 n01 = wn[0], n23 = wn[1];
            u64 n4 = ((const u64*)sw.Wn[k])[4];
            ffma2(an2[0], cp, n01.x); ffma2(an2[1], cp, n01.y);
            ffma2(an2[2], cp, n23.x); ffma2(an2[3], cp, n23.y);
            ffma2(an2[4], cp, n4);
        }
        float yn[NL];
#pragma unroll
        for (int p = 0; p < 5; p++) {
            float2 a = unpack2(an2[p]);
            yn[2 * p]     = a.x + u[2 * p]     * (yo[2 * p]     - a.x);
            yn[2 * p + 1] = a.y + u[2 * p + 1] * (yo[2 * p + 1] - a.y);
        }
#pragma unroll
        for (int k = 0; k < NL; k++) ynp[k] = pack2(yn[k]);

        // ---- fused MLP accumulation ----
        const float* wmrow = &sw.Wm[t * NL][0];
#pragma unroll
        for (int l = 0; l < NL; l++) {
            const ulonglong2* wm = (const ulonglong2*)(wmrow + l * NO);
            ulonglong2 w01 = wm[0], w23 = wm[1];
            ffma2(acc2[0], ynp[l], w01.x);
            ffma2(acc2[1], ynp[l], w01.y);
            ffma2(acc2[2], ynp[l], w23.x);
            ffma2(acc2[3], ynp[l], w23.y);
        }
#pragma unroll
        for (int j = 0; j < NL; j++) y[j] = yn[j];
    }

    // ---- static part + bias ----
    const float* sp = stat + (size_t)b * NS;
#pragma unroll
    for (int s = 0; s < NS; s++) {
        u64 sv = pack2(sp[s]);
        const ulonglong2* wm = (const ulonglong2*)&sw.Wm[NT * NL + s][0];
        ulonglong2 w01 = wm[0], w23 = wm[1];
        ffma2(acc2[0], sv, w01.x);
        ffma2(acc2[1], sv, w01.y);
        ffma2(acc2[2], sv, w23.x);
        ffma2(acc2[3], sv, w23.y);
    }
    float2 a0 = unpack2(acc2[0]), a1 = unpack2(acc2[1]);
    float2 a2 = unpack2(acc2[2]), a3 = unpack2(acc2[3]);
    float4 o0, o1;
    o0.x = a0.x + sw.bm[0]; o0.y = a0.y + sw.bm[1];
    o0.z = a1.x + sw.bm[2]; o0.w = a1.y + sw.bm[3];
    o1.x = a2.x + sw.bm[4]; o1.y = a2.y + sw.bm[5];
    o1.z = a3.x + sw.bm[6]; o1.w = a3.y + sw.bm[7];
    float4* op = reinterpret_cast<float4*>(out + (size_t)b * NO);
    op[0] = o0;
    op[1] = o1;
}

extern "C" void kernel_launch(void* const* d_in, const int* in_sizes, int n_in,
                              void* d_out, int out_size) {
    // Phase A: pre-activation GEMM over all (b, t) rows
    preact_kernel<<<(int)(ROWS / 256), 256>>>(
        (const float*)d_in[0],                            // data
        (const float*)d_in[3], (const float*)d_in[4],     // W_update, b_update
        (const float*)d_in[5], (const float*)d_in[6],     // W_reset,  b_reset
        (const float*)d_in[7], (const float*)d_in[8]);    // W_new,    b_new
    // Phase B: recurrent scan + fused MLP  (W_emit/b_emit are dead code)
    dgm2_kernel<<<NBJ / TPB, TPB>>>(
        (const float*)d_in[1],                            // time_steps
        (const float*)d_in[2],                            // static_data
        (const float*)d_in[3],                            // W_update (yo rows)
        (const float*)d_in[5],                            // W_reset  (yo rows)
        (const float*)d_in[7],                            // W_new    (cand rows)
        (const float*)d_in[11], (const float*)d_in[12],   // W_ode, b_ode
        (const float*)d_in[13], (const float*)d_in[14],   // W_mlp, b_mlp
        (float*)d_out);
}

// round 11
// speedup vs baseline: 1.1446x; 1.1446x over previous
#include <cuda_runtime.h>
#include <cstdint>

#define NT 60
#define ND 36
#define NL 10
#define NS 9
#define NO 8
#define MIN_ (NT*NL + NS) // 609
#define TPB 64
#define NBJ 16384
#define ROWS ((size_t)NBJ * NT)   // 983040

typedef unsigned long long u64;

// 126 MB scratch: per (b,t) row of 32 floats: au[10]*L2E, ar[10]*L2E, an[10], pad[2]
__device__ __align__(128) float g_pre[ROWS * 32];

__device__ __forceinline__ float ex2(float x) {
    float r; asm("ex2.approx.ftz.f32 %0, %1;" : "=f"(r) : "f"(x)); return r;
}
__device__ __forceinline__ float frcp(float x) {
    float r; asm("rcp.approx.ftz.f32 %0, %1;" : "=f"(r) : "f"(x)); return r;
}
__device__ __forceinline__ void ffma2(u64& d, u64 a, u64 b) {
    asm("fma.rn.f32x2 %0, %1, %2, %0;" : "+l"(d) : "l"(a), "l"(b));
}
__device__ __forceinline__ u64 pack2(float v) {
    u64 r; asm("mov.b64 %0, {%1, %1};" : "=l"(r) : "f"(v)); return r;
}
__device__ __forceinline__ float2 unpack2(u64 v) {
    float2 f; asm("mov.b64 {%0, %1}, %2;" : "=f"(f.x), "=f"(f.y) : "l"(v)); return f;
}
__device__ __forceinline__ uint32_t smem_u32(const void* p) {
    return (uint32_t)__cvta_generic_to_shared(p);
}
__device__ __forceinline__ void cpasync16(uint32_t dst, const float* src) {
    asm volatile("cp.async.cg.shared.global [%0], [%1], 16;" :: "r"(dst), "l"(src));
}
__device__ __forceinline__ void cpcommit() {
    asm volatile("cp.async.commit_group;" ::: "memory");
}
template<int N> __device__ __forceinline__ void cpwait() {
    asm volatile("cp.async.wait_group %0;" :: "n"(N) : "memory");
}

// ============================================================================
// Kernel A: pre-activation GEMM. 128 threads/block, 2 rows/thread (rows tid
// and tid+128 of a 256-row tile) — weight LDS amortized over both rows.
//   row r = (b*NT + t): [ (x@WuX+bu)*L2E | (x@WrX+br)*L2E | x@WnX+bn | pad2 ]
// ============================================================================
__global__ __launch_bounds__(128) void preact_kernel(
    const float* __restrict__ data,
    const float* __restrict__ gWu, const float* __restrict__ gbu,
    const float* __restrict__ gWr, const float* __restrict__ gbr,
    const float* __restrict__ gWn, const float* __restrict__ gbn)
{
    __shared__ __align__(16) float W[ND][32];      // [k][u(10) r(10) n(10) pad2]
    __shared__ __align__(16) float bias[32];
    __shared__ __align__(16) float buf[256 * 37];  // in: 256 rows pad-37; out: pad-33
    const int tid = threadIdx.x;
    const float L2E = 1.4426950408889634f;

    for (int i = tid; i < ND * NL; i += 128) {
        int k = i / NL, j = i - k * NL;
        W[k][j]      = gWu[(NL + k) * NL + j] * L2E;
        W[k][10 + j] = gWr[(NL + k) * NL + j] * L2E;
        W[k][20 + j] = gWn[(NL + k) * NL + j];
    }
    for (int i = tid; i < ND * 2; i += 128) W[i / 2][30 + (i & 1)] = 0.f;
    if (tid < NL) {
        bias[tid]      = gbu[tid] * L2E;
        bias[10 + tid] = gbr[tid] * L2E;
        bias[20 + tid] = gbn[tid];
    }
    if (tid < 2) bias[30 + tid] = 0.f;

    // ---- coalesced load of 256 contiguous rows (36 KB) into padded smem ----
    const size_t fbase = (size_t)blockIdx.x * 256 * ND;
    const float4* src4 = reinterpret_cast<const float4*>(data + fbase);
#pragma unroll
    for (int i = 0; i < 18; i++) {                 // 2304 float4 / 128 threads
        float4 v = src4[tid + 128 * i];
        int g = 4 * (tid + 128 * i);
        float vv[4] = {v.x, v.y, v.z, v.w};
#pragma unroll
        for (int j = 0; j < 4; j++) {
            int gg = g + j;
            buf[gg + gg / ND] = vv[j];             // row*37 + col
        }
    }
    __syncthreads();

    // ---- compute: 2 rows/thread, shared weight row loaded once per k ----
    const float* x0 = buf + tid * 37;
    const float* x1 = buf + (tid + 128) * 37;
    u64 a0[15], a1[15];
    const u64* bp = (const u64*)bias;
#pragma unroll
    for (int p = 0; p < 15; p++) { a0[p] = bp[p]; a1[p] = bp[p]; }

#pragma unroll 6
    for (int k = 0; k < ND; k++) {
        u64 xp0 = pack2(x0[k]);
        u64 xp1 = pack2(x1[k]);
        const ulonglong2* w2 = (const ulonglong2*)W[k];
        ulonglong2 wa = w2[0], wb = w2[1], wc = w2[2];
        ulonglong2 wd = w2[3], we_ = w2[4], wf = w2[5], wg = w2[6];
        u64 w14 = ((const u64*)W[k])[14];
        ffma2(a0[0],  xp0, wa.x);  ffma2(a1[0],  xp1, wa.x);
        ffma2(a0[1],  xp0, wa.y);  ffma2(a1[1],  xp1, wa.y);
        ffma2(a0[2],  xp0, wb.x);  ffma2(a1[2],  xp1, wb.x);
        ffma2(a0[3],  xp0, wb.y);  ffma2(a1[3],  xp1, wb.y);
        ffma2(a0[4],  xp0, wc.x);  ffma2(a1[4],  xp1, wc.x);
        ffma2(a0[5],  xp0, wc.y);  ffma2(a1[5],  xp1, wc.y);
        ffma2(a0[6],  xp0, wd.x);  ffma2(a1[6],  xp1, wd.x);
        ffma2(a0[7],  xp0, wd.y);  ffma2(a1[7],  xp1, wd.y);
        ffma2(a0[8],  xp0, we_.x); ffma2(a1[8],  xp1, we_.x);
        ffma2(a0[9],  xp0, we_.y); ffma2(a1[9],  xp1, we_.y);
        ffma2(a0[10], xp0, wf.x);  ffma2(a1[10], xp1, wf.x);
        ffma2(a0[11], xp0, wf.y);  ffma2(a1[11], xp1, wf.y);
        ffma2(a0[12], xp0, wg.x);  ffma2(a1[12], xp1, wg.x);
        ffma2(a0[13], xp0, wg.y);  ffma2(a1[13], xp1, wg.y);
        ffma2(a0[14], xp0, w14);   ffma2(a1[14], xp1, w14);
    }
    __syncthreads();   // input tile reads done; reuse buf as output staging

    // ---- write both rows to padded-33 smem (rows tid, tid+128: conflict-free) ----
    float* o0 = buf + tid * 33;
    float* o1 = buf + (tid + 128) * 33;
#pragma unroll
    for (int p = 0; p < 15; p++) {
        float2 f0 = unpack2(a0[p]);
        float2 f1 = unpack2(a1[p]);
        o0[2 * p] = f0.x; o0[2 * p + 1] = f0.y;
        o1[2 * p] = f1.x; o1[2 * p + 1] = f1.y;
    }
    o0[30] = 0.f; o0[31] = 0.f;
    o1[30] = 0.f; o1[31] = 0.f;
    __syncthreads();

    // ---- coalesced store of the 32 KB output tile ----
    float4* dst4 = reinterpret_cast<float4*>(g_pre + (size_t)blockIdx.x * 256 * 32);
#pragma unroll
    for (int i = 0; i < 16; i++) {                 // 2048 float4 / 128 threads
        int g4 = tid + 128 * i;
        int rl = g4 >> 3, q = g4 & 7;
        const float* s = buf + rl * 33 + q * 4;
        dst4[g4] = make_float4(s[0], s[1], s[2], s[3]);
    }
}

// ============================================================================
// Kernel B: recurrent scan (unchanged — 77 us verified)
// ============================================================================
struct __align__(16) SWB {
    float Wu[NL][12];     // yo-part rows, ×L2E
    float Wr[NL][12];     // ×L2E
    float Wn[NL][12];     // candidate rows, unscaled
    float Wo[NL][12];     // ×2*L2E
    float Wm[MIN_][NO];
    float bo[12];         // ×2*L2E
    float bm[NO];
    float dts[NT];
};

__global__ __launch_bounds__(TPB) void dgm2_kernel(
    const float* __restrict__ ts,
    const float* __restrict__ stat,
    const float* __restrict__ gWu,
    const float* __restrict__ gWr,
    const float* __restrict__ gWn,
    const float* __restrict__ gWo, const float* __restrict__ gbo,
    const float* __restrict__ gWm, const float* __restrict__ gbm,
    float* __restrict__ out)
{
    __shared__ SWB sw;
    __shared__ __align__(16) u64 pre[2][8][TPB][2];
    const int tid = threadIdx.x;
    const float L2E = 1.4426950408889634f;

    for (int i = tid; i < NL * NL; i += TPB) {
        int r = i / NL, c = i - r * NL;
        sw.Wu[r][c] = gWu[i] * L2E;
        sw.Wr[r][c] = gWr[i] * L2E;
        sw.Wn[r][c] = gWn[i];
        sw.Wo[r][c] = gWo[i] * (2.f * L2E);
    }
    for (int i = tid; i < MIN_ * NO; i += TPB) (&sw.Wm[0][0])[i] = gWm[i];
    if (tid < 12) sw.bo[tid] = 0.f;
    __syncthreads();
    if (tid < NL) sw.bo[tid] = gbo[tid] * (2.f * L2E);
    if (tid < NO) sw.bm[tid] = gbm[tid];
    for (int i = tid; i < NT; i += TPB)
        sw.dts[i] = (i == 0) ? 0.01f : (ts[i] - ts[i - 1]);
    __syncthreads();

    const int b = blockIdx.x * TPB + tid;
    const float* pg = g_pre + (size_t)b * NT * 32;

#pragma unroll
    for (int c = 0; c < 8; c++)
        cpasync16(smem_u32(&pre[0][c][tid][0]), pg + 4 * c);
    cpcommit();

    float y[NL];
    u64 ynp[NL];
    u64 acc2[4];
#pragma unroll
    for (int j = 0; j < NL; j++) { y[j] = 0.f; ynp[j] = 0ull; }
#pragma unroll
    for (int o = 0; o < 4; o++) acc2[o] = 0ull;

    const u64* bop = (const u64*)sw.bo;

#pragma unroll 1
    for (int t = 0; t < NT; t++) {
        if (t + 1 < NT) {
            const int nb = (t + 1) & 1;
            const float* src = pg + (size_t)(t + 1) * 32;
#pragma unroll
            for (int c = 0; c < 8; c++)
                cpasync16(smem_u32(&pre[nb][c][tid][0]), src + 4 * c);
            cpcommit();
            cpwait<1>();
        } else {
            cpwait<0>();
        }
        const float dt = sw.dts[t];
        const float dt2 = 2.f * dt;

        // ---- ODE Euler ----
        u64 og2[5];
#pragma unroll
        for (int p = 0; p < 5; p++) og2[p] = bop[p];
#pragma unroll
        for (int k = 0; k < NL; k++) {
            const ulonglong2* w = (const ulonglong2*)sw.Wo[k];
            ulonglong2 w01 = w[0], w23 = w[1];
            u64 w4 = ((const u64*)sw.Wo[k])[4];
            ffma2(og2[0], ynp[k], w01.x);
            ffma2(og2[1], ynp[k], w01.y);
            ffma2(og2[2], ynp[k], w23.x);
            ffma2(og2[3], ynp[k], w23.y);
            ffma2(og2[4], ynp[k], w4);
        }
        float yo[NL];
#pragma unroll
        for (int p = 0; p < 5; p++) {
            float2 g = unpack2(og2[p]);
            yo[2 * p]     = (y[2 * p] + dt)     - dt2 * frcp(ex2(g.x) + 1.f);
            yo[2 * p + 1] = (y[2 * p + 1] + dt) - dt2 * frcp(ex2(g.y) + 1.f);
        }
        u64 yop[NL];
#pragma unroll
        for (int k = 0; k < NL; k++) yop[k] = pack2(yo[k]);

        // ---- gate accumulators init from streamed pre-activations ----
        u64 pv[16];
        const int cb = t & 1;
#pragma unroll
        for (int c = 0; c < 8; c++) {
            ulonglong2 v = *(const ulonglong2*)&pre[cb][c][tid][0];
            pv[2 * c] = v.x; pv[2 * c + 1] = v.y;
        }
        u64 au2[5], ar2[5], an2[5];
#pragma unroll
        for (int p = 0; p < 5; p++) {
            au2[p] = pv[p];
            ar2[p] = pv[5 + p];
            an2[p] = pv[10 + p];
        }

        // yo part for update/reset
#pragma unroll
        for (int k = 0; k < NL; k++) {
            const ulonglong2* wu = (const ulonglong2*)sw.Wu[k];
            const ulonglong2* wr = (const ulonglong2*)sw.Wr[k];
            ulonglong2 u01 = wu[0], u23 = wu[1];
            ulonglong2 r01 = wr[0], r23 = wr[1];
            u64 u4 = ((const u64*)sw.Wu[k])[4];
            u64 r4 = ((const u64*)sw.Wr[k])[4];
            ffma2(au2[0], yop[k], u01.x); ffma2(au2[1], yop[k], u01.y);
            ffma2(au2[2], yop[k], u23.x); ffma2(au2[3], yop[k], u23.y);
            ffma2(au2[4], yop[k], u4);
            ffma2(ar2[0], yop[k], r01.x); ffma2(ar2[1], yop[k], r01.y);
            ffma2(ar2[2], yop[k], r23.x); ffma2(ar2[3], yop[k], r23.y);
            ffma2(ar2[4], yop[k], r4);
        }
        // sigmoid (inputs pre-scaled by log2e)
        float u[NL], r[NL];
#pragma unroll
        for (int p = 0; p < 5; p++) {
            float2 a = unpack2(au2[p]);
            float2 rr = unpack2(ar2[p]);
            u[2 * p]     = frcp(1.f + ex2(-a.x));
            u[2 * p + 1] = frcp(1.f + ex2(-a.y));
            r[2 * p]     = frcp(1.f + ex2(-rr.x));
            r[2 * p + 1] = frcp(1.f + ex2(-rr.y));
        }
        // candidate (yo*r part)
#pragma unroll
        for (int k = 0; k < NL; k++) {
            u64 cp = pack2(yo[k] * r[k]);
            const ulonglong2* wn = (const ulonglong2*)sw.Wn[k];
            ulonglong2 n01 = wn[0], n23 = wn[1];
            u64 n4 = ((const u64*)sw.Wn[k])[4];
            ffma2(an2[0], cp, n01.x); ffma2(an2[1], cp, n01.y);
            ffma2(an2[2], cp, n23.x); ffma2(an2[3], cp, n23.y);
            ffma2(an2[4], cp, n4);
        }
        float yn[NL];
#pragma unroll
        for (int p = 0; p < 5; p++) {
            float2 a = unpack2(an2[p]);
            yn[2 * p]     = a.x + u[2 * p]     * (yo[2 * p]     - a.x);
            yn[2 * p + 1] = a.y + u[2 * p + 1] * (yo[2 * p + 1] - a.y);
        }
#pragma unroll
        for (int k = 0; k < NL; k++) ynp[k] = pack2(yn[k]);

        // ---- fused MLP accumulation ----
        const float* wmrow = &sw.Wm[t * NL][0];
#pragma unroll
        for (int l = 0; l < NL; l++) {
            const ulonglong2* wm = (const ulonglong2*)(wmrow + l * NO);
            ulonglong2 w01 = wm[0], w23 = wm[1];
            ffma2(acc2[0], ynp[l], w01.x);
            ffma2(acc2[1], ynp[l], w01.y);
            ffma2(acc2[2], ynp[l], w23.x);
            ffma2(acc2[3], ynp[l], w23.y);
        }
#pragma unroll
        for (int j = 0; j < NL; j++) y[j] = yn[j];
    }

    // ---- static part + bias ----
    const float* sp = stat + (size_t)b * NS;
#pragma unroll
    for (int s = 0; s < NS; s++) {
        u64 sv = pack2(sp[s]);
        const ulonglong2* wm = (const ulonglong2*)&sw.Wm[NT * NL + s][0];
        ulonglong2 w01 = wm[0], w23 = wm[1];
        ffma2(acc2[0], sv, w01.x);
        ffma2(acc2[1], sv, w01.y);
        ffma2(acc2[2], sv, w23.x);
        ffma2(acc2[3], sv, w23.y);
    }
    float2 a0 = unpack2(acc2[0]), a1 = unpack2(acc2[1]);
    float2 a2 = unpack2(acc2[2]), a3 = unpack2(acc2[3]);
    float4 o0, o1;
    o0.x = a0.x + sw.bm[0]; o0.y = a0.y + sw.bm[1];
    o0.z = a1.x + sw.bm[2]; o0.w = a1.y + sw.bm[3];
    o1.x = a2.x + sw.bm[4]; o1.y = a2.y + sw.bm[5];
    o1.z = a3.x + sw.bm[6]; o1.w = a3.y + sw.bm[7];
    float4* op = reinterpret_cast<float4*>(out + (size_t)b * NO);
    op[0] = o0;
    op[1] = o1;
}

extern "C" void kernel_launch(void* const* d_in, const int* in_sizes, int n_in,
                              void* d_out, int out_size) {
    // Phase A: pre-activation GEMM (256 rows per block, 2 rows per thread)
    preact_kernel<<<(int)(ROWS / 256), 128>>>(
        (const float*)d_in[0],                            // data
        (const float*)d_in[3], (const float*)d_in[4],     // W_update, b_update
        (const float*)d_in[5], (const float*)d_in[6],     // W_reset,  b_reset
        (const float*)d_in[7], (const float*)d_in[8]);    // W_new,    b_new
    // Phase B: recurrent scan + fused MLP  (W_emit/b_emit are dead code)
    dgm2_kernel<<<NBJ / TPB, TPB>>>(
        (const float*)d_in[1],                            // time_steps
        (const float*)d_in[2],                            // static_data
        (const float*)d_in[3],                            // W_update (yo rows)
        (const float*)d_in[5],                            // W_reset  (yo rows)
        (const float*)d_in[7],                            // W_new    (cand rows)
        (const float*)d_in[11], (const float*)d_in[12],   // W_ode, b_ode
        (const float*)d_in[13], (const float*)d_in[14],   // W_mlp, b_mlp
        (float*)d_out);
}